// round 11
// baseline (speedup 1.0000x reference)
#include <cuda_runtime.h>
#include <cuda_bf16.h>
#include <cuda_fp16.h>
#include <cstdint>

// ============================================================================
// out[b,o] = log( sum_k e^x[b,k] * e^w[o,k] ) - log( sum_k e^w[o,k] )
// GEMM: 256 blocks x 256 threads, 2 CTAs/SM (K-split, no duplicated work),
// single smem stage per block (K=64), bf16 mma.sync, fp16 partials.
// Finalize: 128 blocks x 1024 threads, PDL-launched.
// ============================================================================

#define B_DIM  128
#define O_DIM  128
#define K_DIM  16384
#define NSPLIT 256
#define KCHUNK 64
#define LDSR   72     // smem row stride (bf16): 144B -> 16B-aligned, conflict-free

__device__ __half2 g_part[NSPLIT * B_DIM * (O_DIM / 2)];  // [sp][b][o2] 8MB
__device__ float   g_rpart[NSPLIT * O_DIM];               // [sp][o] 128KB

__device__ __forceinline__ uint32_t smem_u32(const void* p) {
    return (uint32_t)__cvta_generic_to_shared(p);
}
__device__ __forceinline__ uint32_t bf2_bits(__nv_bfloat162 v) {
    union { __nv_bfloat162 h; uint32_t u; } cvt; cvt.h = v; return cvt.u;
}

__global__ __launch_bounds__(256, 2)
void srl_gemm_kernel(const float* __restrict__ x, const float* __restrict__ w) {
    __shared__ __align__(16) __nv_bfloat16 sA[B_DIM * LDSR];   // 18KB
    __shared__ __align__(16) __nv_bfloat16 sB[B_DIM * LDSR];   // 18KB

    const int tid  = threadIdx.x;
    const int lane = tid & 31;
    const int wid  = tid >> 5;          // 0..7
    const int sp   = blockIdx.x;        // K-split index
    const int kbase = sp * KCHUNK;

    // Loaders: 2 threads per row, each owns 32 contiguous floats (8 x float4).
    const int row = tid >> 1;
    const int kh  = tid & 1;
    const float4* xp4 = (const float4*)(x + (size_t)row * K_DIM + kbase + kh * 32);
    const float4* wp4 = (const float4*)(w + (size_t)row * K_DIM + kbase + kh * 32);

    // Load everything first (16 independent LDG.128 -> high MLP).
    float4 rx[8], rw[8];
#pragma unroll
    for (int j = 0; j < 8; j++) rx[j] = xp4[j];
#pragma unroll
    for (int j = 0; j < 8; j++) rw[j] = wp4[j];

    // exp + bf16 convert + smem store.
    uint2* adst = (uint2*)&sA[row * LDSR + kh * 32];
    uint2* bdst = (uint2*)&sB[row * LDSR + kh * 32];
    float rsum = 0.f;
#pragma unroll
    for (int j = 0; j < 8; j++) {
        float ax = __expf(rx[j].x), ay = __expf(rx[j].y);
        float az = __expf(rx[j].z), aw = __expf(rx[j].w);
        uint2 av;
        av.x = bf2_bits(__floats2bfloat162_rn(ax, ay));
        av.y = bf2_bits(__floats2bfloat162_rn(az, aw));
        adst[j] = av;
        float bx = __expf(rw[j].x), by = __expf(rw[j].y);
        float bz = __expf(rw[j].z), bw = __expf(rw[j].w);
        rsum += (bx + by) + (bz + bw);
        uint2 bv;
        bv.x = bf2_bits(__floats2bfloat162_rn(bx, by));
        bv.y = bf2_bits(__floats2bfloat162_rn(bz, bw));
        bdst[j] = bv;
    }

    // rsum: 2 threads per w-row -> pair reduce, store partial row-sum.
    rsum += __shfl_xor_sync(0xffffffffu, rsum, 1);
    if (kh == 0) g_rpart[sp * O_DIM + row] = rsum;

    __syncthreads();   // the ONLY barrier in the kernel

    // 8 warps: 2(m) x 4(n) grid of 64x32 tiles covering 128x128.
    const int m0 = (wid >> 2) * 64;
    const int n0 = (wid & 3) * 32;

    float acc[4][4][4];
#pragma unroll
    for (int mi = 0; mi < 4; mi++)
#pragma unroll
        for (int nj = 0; nj < 4; nj++)
#pragma unroll
            for (int q = 0; q < 4; q++) acc[mi][nj][q] = 0.f;

#pragma unroll
    for (int ks = 0; ks < KCHUNK; ks += 16) {
        uint32_t af[4][4];
#pragma unroll
        for (int mi = 0; mi < 4; mi++) {
            int ar = m0 + mi * 16 + (lane & 15);
            int ac = ks + (lane >> 4) * 8;
            uint32_t addr = smem_u32(&sA[ar * LDSR + ac]);
            asm volatile(
                "ldmatrix.sync.aligned.m8n8.x4.shared.b16 {%0,%1,%2,%3}, [%4];"
                : "=r"(af[mi][0]), "=r"(af[mi][1]), "=r"(af[mi][2]), "=r"(af[mi][3])
                : "r"(addr));
        }
        uint32_t bfr[2][4];
#pragma unroll
        for (int nb = 0; nb < 2; nb++) {
            int g = lane >> 3, r = lane & 7;
            int br = n0 + nb * 16 + (g >> 1) * 8 + r;
            int bc = ks + (g & 1) * 8;
            uint32_t addr = smem_u32(&sB[br * LDSR + bc]);
            asm volatile(
                "ldmatrix.sync.aligned.m8n8.x4.shared.b16 {%0,%1,%2,%3}, [%4];"
                : "=r"(bfr[nb][0]), "=r"(bfr[nb][1]), "=r"(bfr[nb][2]), "=r"(bfr[nb][3])
                : "r"(addr));
        }
#pragma unroll
        for (int mi = 0; mi < 4; mi++)
#pragma unroll
            for (int nj = 0; nj < 4; nj++) {
                uint32_t b0 = bfr[nj >> 1][(nj & 1) * 2 + 0];
                uint32_t b1 = bfr[nj >> 1][(nj & 1) * 2 + 1];
                asm volatile(
                    "mma.sync.aligned.m16n8k16.row.col.f32.bf16.bf16.f32 "
                    "{%0,%1,%2,%3}, {%4,%5,%6,%7}, {%8,%9}, {%0,%1,%2,%3};"
                    : "+f"(acc[mi][nj][0]), "+f"(acc[mi][nj][1]),
                      "+f"(acc[mi][nj][2]), "+f"(acc[mi][nj][3])
                    : "r"(af[mi][0]), "r"(af[mi][1]), "r"(af[mi][2]), "r"(af[mi][3]),
                      "r"(b0), "r"(b1));
            }
    }

    // fp16 partial tile [sp][b][o2]
    __half2* dst = g_part + (size_t)sp * (B_DIM * 64);
#pragma unroll
    for (int mi = 0; mi < 4; mi++)
#pragma unroll
        for (int nj = 0; nj < 4; nj++) {
            int gr = m0 + mi * 16 + (lane >> 2);
            int gc = n0 + nj * 8 + (lane & 3) * 2;
            dst[gr * 64 + (gc >> 1)] =
                __floats2half2_rn(acc[mi][nj][0], acc[mi][nj][1]);
            dst[(gr + 8) * 64 + (gc >> 1)] =
                __floats2half2_rn(acc[mi][nj][2], acc[mi][nj][3]);
        }

    cudaTriggerProgrammaticLaunchCompletion();
}

// Finalize: block b; 32 sp-groups x 32 o4-slots; 8 splits per group; PDL.
__global__ __launch_bounds__(1024)
void srl_finalize_kernel(float* __restrict__ out) {
    const int b  = blockIdx.x;
    const int t  = threadIdx.x;
    const int o4 = t & 31;        // outputs 4*o4 .. 4*o4+3
    const int sg = t >> 5;        // 0..31

    const __half2* pbase = g_part + (size_t)b * 64 + o4 * 2;
    cudaGridDependencySynchronize();

    float s0 = 0.f, s1 = 0.f, s2 = 0.f, s3 = 0.f;
    float r0 = 0.f, r1 = 0.f, r2 = 0.f, r3 = 0.f;
#pragma unroll
    for (int i = 0; i < 8; i++) {
        int sp = sg + 32 * i;
        uint2 pv = *(const uint2*)(pbase + (size_t)sp * (B_DIM * 64));
        union { uint32_t u; __half2 h; } c0, c1;
        c0.u = pv.x; c1.u = pv.y;
        float2 v0 = __half22float2(c0.h);
        float2 v1 = __half22float2(c1.h);
        s0 += v0.x; s1 += v0.y; s2 += v1.x; s3 += v1.y;
        float4 rv = *(const float4*)&g_rpart[sp * O_DIM + o4 * 4];
        r0 += rv.x; r1 += rv.y; r2 += rv.z; r3 += rv.w;
    }

    __shared__ float ss[32 * 128];
    __shared__ float sr[32 * 128];
    *(float4*)&ss[sg * 128 + o4 * 4] = make_float4(s0, s1, s2, s3);
    *(float4*)&sr[sg * 128 + o4 * 4] = make_float4(r0, r1, r2, r3);
    __syncthreads();

    if (t < 128) {
        float S = 0.f, R = 0.f;
#pragma unroll
        for (int i = 0; i < 32; i++) {
            S += ss[i * 128 + t];
            R += sr[i * 128 + t];
        }
        out[b * O_DIM + t] = __logf(S) - __logf(R);
    }
}

extern "C" void kernel_launch(void* const* d_in, const int* in_sizes, int n_in,
                              void* d_out, int out_size) {
    (void)in_sizes; (void)n_in; (void)out_size;
    const float* x = (const float*)d_in[0];   // [128, 16384]
    const float* w = (const float*)d_in[1];   // [128, 16384]
    float* out = (float*)d_out;               // [128, 128]

    srl_gemm_kernel<<<NSPLIT, 256>>>(x, w);

    cudaLaunchConfig_t cfg = {};
    cfg.gridDim  = dim3(B_DIM);
    cfg.blockDim = dim3(1024);
    cfg.dynamicSmemBytes = 0;
    cfg.stream = 0;
    cudaLaunchAttribute attr[1];
    attr[0].id = cudaLaunchAttributeProgrammaticStreamSerialization;
    attr[0].val.programmaticStreamSerializationAllowed = 1;
    cfg.attrs = attr;
    cfg.numAttrs = 1;
    cudaLaunchKernelEx(&cfg, srl_finalize_kernel, out);
}

// round 12
// speedup vs baseline: 1.1225x; 1.1225x over previous
#include <cuda_runtime.h>
#include <cuda_bf16.h>
#include <cuda_fp16.h>
#include <cstdint>

// ============================================================================
// out[b,o] = log( sum_k e^x[b,k] * e^w[o,k] ) - log( sum_k e^w[o,k] )
// R4 GEMM (measured best: 128 blocks x 512 thr, 4-stage double-buffered bf16
// mma.sync, fp16 partials) + 256-thread PDL finalize that can CO-RESIDE with
// the GEMM (reg/smem budget checked), so launch+ramp hides under GEMM tail.
// ============================================================================

#define B_DIM  128
#define O_DIM  128
#define K_DIM  16384
#define NSPLIT 128
#define KCHUNK 128
#define NSUB   4
#define KSUB   32
#define LDSR   40     // smem row stride (bf16): 80B, conflict-free ldmatrix

__device__ __half2 g_part[NSPLIT * B_DIM * (O_DIM / 2)];  // [sp][b][o2] 4MB
__device__ float   g_rpart[NSPLIT * O_DIM];               // [sp][o]

__device__ __forceinline__ uint32_t smem_u32(const void* p) {
    return (uint32_t)__cvta_generic_to_shared(p);
}
__device__ __forceinline__ uint32_t bf2_bits(__nv_bfloat162 v) {
    union { __nv_bfloat162 h; uint32_t u; } cvt; cvt.h = v; return cvt.u;
}

__global__ __launch_bounds__(512, 1)
void srl_gemm_kernel(const float* __restrict__ x, const float* __restrict__ w) {
    __shared__ __align__(16) __nv_bfloat16 sA[2][B_DIM * LDSR];
    __shared__ __align__(16) __nv_bfloat16 sB[2][B_DIM * LDSR];

    const int tid  = threadIdx.x;
    const int lane = tid & 31;
    const int wid  = tid >> 5;
    const int bid  = blockIdx.x;
    const int kbase = bid * KCHUNK;

    const int lrow = tid >> 2;
    const int kq   = tid & 3;
    const float4* xp4 = (const float4*)(x + (size_t)lrow * K_DIM + kbase + kq * 8);
    const float4* wp4 = (const float4*)(w + (size_t)lrow * K_DIM + kbase + kq * 8);

    const int m0 = (wid >> 2) * 32;
    const int n0 = (wid & 3) * 32;

    float acc[2][4][4];
#pragma unroll
    for (int mi = 0; mi < 2; mi++)
#pragma unroll
        for (int nj = 0; nj < 4; nj++)
#pragma unroll
            for (int q = 0; q < 4; q++) acc[mi][nj][q] = 0.f;

    float4 rx[2], rw[2];
#pragma unroll
    for (int j = 0; j < 2; j++) { rx[j] = xp4[j]; rw[j] = wp4[j]; }

    float rsum = 0.f;

    for (int sub = 0; sub < NSUB; ++sub) {
        const int buf = sub & 1;
        const bool has_next = (sub + 1 < NSUB);

        uint2* adst = (uint2*)&sA[buf][lrow * LDSR + kq * 8];
        uint2* bdst = (uint2*)&sB[buf][lrow * LDSR + kq * 8];
#pragma unroll
        for (int j = 0; j < 2; j++) {
            float ax = __expf(rx[j].x), ay = __expf(rx[j].y);
            float az = __expf(rx[j].z), aw = __expf(rx[j].w);
            if (has_next) rx[j] = xp4[(sub + 1) * 8 + j];
            uint2 av;
            av.x = bf2_bits(__floats2bfloat162_rn(ax, ay));
            av.y = bf2_bits(__floats2bfloat162_rn(az, aw));
            adst[j] = av;
            float bx = __expf(rw[j].x), by = __expf(rw[j].y);
            float bz = __expf(rw[j].z), bw = __expf(rw[j].w);
            if (has_next) rw[j] = wp4[(sub + 1) * 8 + j];
            rsum += (bx + by) + (bz + bw);
            uint2 bv;
            bv.x = bf2_bits(__floats2bfloat162_rn(bx, by));
            bv.y = bf2_bits(__floats2bfloat162_rn(bz, bw));
            bdst[j] = bv;
        }

        __syncthreads();

#pragma unroll
        for (int ks = 0; ks < KSUB; ks += 16) {
            uint32_t af[2][4];
#pragma unroll
            for (int mi = 0; mi < 2; mi++) {
                int ar = m0 + mi * 16 + (lane & 15);
                int ac = ks + (lane >> 4) * 8;
                uint32_t addr = smem_u32(&sA[buf][ar * LDSR + ac]);
                asm volatile(
                    "ldmatrix.sync.aligned.m8n8.x4.shared.b16 {%0,%1,%2,%3}, [%4];"
                    : "=r"(af[mi][0]), "=r"(af[mi][1]), "=r"(af[mi][2]), "=r"(af[mi][3])
                    : "r"(addr));
            }
            uint32_t bfr[2][4];
#pragma unroll
            for (int nb = 0; nb < 2; nb++) {
                int g = lane >> 3, r = lane & 7;
                int br = n0 + nb * 16 + (g >> 1) * 8 + r;
                int bc = ks + (g & 1) * 8;
                uint32_t addr = smem_u32(&sB[buf][br * LDSR + bc]);
                asm volatile(
                    "ldmatrix.sync.aligned.m8n8.x4.shared.b16 {%0,%1,%2,%3}, [%4];"
                    : "=r"(bfr[nb][0]), "=r"(bfr[nb][1]), "=r"(bfr[nb][2]), "=r"(bfr[nb][3])
                    : "r"(addr));
            }
#pragma unroll
            for (int mi = 0; mi < 2; mi++)
#pragma unroll
                for (int nj = 0; nj < 4; nj++) {
                    uint32_t b0 = bfr[nj >> 1][(nj & 1) * 2 + 0];
                    uint32_t b1 = bfr[nj >> 1][(nj & 1) * 2 + 1];
                    asm volatile(
                        "mma.sync.aligned.m16n8k16.row.col.f32.bf16.bf16.f32 "
                        "{%0,%1,%2,%3}, {%4,%5,%6,%7}, {%8,%9}, {%0,%1,%2,%3};"
                        : "+f"(acc[mi][nj][0]), "+f"(acc[mi][nj][1]),
                          "+f"(acc[mi][nj][2]), "+f"(acc[mi][nj][3])
                        : "r"(af[mi][0]), "r"(af[mi][1]), "r"(af[mi][2]), "r"(af[mi][3]),
                          "r"(b0), "r"(b1));
                }
        }
    }

    rsum += __shfl_xor_sync(0xffffffffu, rsum, 1);
    rsum += __shfl_xor_sync(0xffffffffu, rsum, 2);
    if (kq == 0) g_rpart[bid * O_DIM + lrow] = rsum;

#pragma unroll
    for (int mi = 0; mi < 2; mi++)
#pragma unroll
        for (int nj = 0; nj < 4; nj++) {
            int gr = m0 + mi * 16 + (lane >> 2);
            int gc = n0 + nj * 8 + (lane & 3) * 2;
            g_part[(size_t)bid * (B_DIM * 64) + gr * 64 + (gc >> 1)] =
                __floats2half2_rn(acc[mi][nj][0], acc[mi][nj][1]);
            g_part[(size_t)bid * (B_DIM * 64) + (gr + 8) * 64 + (gc >> 1)] =
                __floats2half2_rn(acc[mi][nj][2], acc[mi][nj][3]);
        }

    cudaTriggerProgrammaticLaunchCompletion();
}

// Finalize: 128 blocks x 256 threads (CO-RESIDENT with GEMM under PDL:
// 256 x ~40 regs = 10K regs + GEMM's 54K < 64K; 8KB smem + 40KB < 228KB).
// 8 sp-groups x 16 splits; prologue runs before the grid dependency resolves.
__global__ __launch_bounds__(256)
void srl_finalize_kernel(float* __restrict__ out) {
    const int b  = blockIdx.x;
    const int t  = threadIdx.x;
    const int o4 = t & 31;        // outputs 4*o4 .. 4*o4+3
    const int sg = t >> 5;        // 0..7

    const __half2* pbase = g_part + (size_t)b * 64 + o4 * 2;
    cudaGridDependencySynchronize();

    float s0 = 0.f, s1 = 0.f, s2 = 0.f, s3 = 0.f;
    float r0 = 0.f, r1 = 0.f, r2 = 0.f, r3 = 0.f;
#pragma unroll
    for (int i = 0; i < 16; i++) {
        int sp = sg + 8 * i;
        uint2 pv = *(const uint2*)(pbase + (size_t)sp * (B_DIM * 64));
        union { uint32_t u; __half2 h; } c0, c1;
        c0.u = pv.x; c1.u = pv.y;
        float2 v0 = __half22float2(c0.h);
        float2 v1 = __half22float2(c1.h);
        s0 += v0.x; s1 += v0.y; s2 += v1.x; s3 += v1.y;
        float4 rv = *(const float4*)&g_rpart[sp * O_DIM + o4 * 4];
        r0 += rv.x; r1 += rv.y; r2 += rv.z; r3 += rv.w;
    }

    __shared__ float ss[8 * 128];
    __shared__ float sr[8 * 128];
    *(float4*)&ss[sg * 128 + o4 * 4] = make_float4(s0, s1, s2, s3);
    *(float4*)&sr[sg * 128 + o4 * 4] = make_float4(r0, r1, r2, r3);
    __syncthreads();

    if (t < 128) {
        float S = 0.f, R = 0.f;
#pragma unroll
        for (int i = 0; i < 8; i++) {
            S += ss[i * 128 + t];
            R += sr[i * 128 + t];
        }
        out[b * O_DIM + t] = __logf(S) - __logf(R);
    }
}

extern "C" void kernel_launch(void* const* d_in, const int* in_sizes, int n_in,
                              void* d_out, int out_size) {
    (void)in_sizes; (void)n_in; (void)out_size;
    const float* x = (const float*)d_in[0];   // [128, 16384]
    const float* w = (const float*)d_in[1];   // [128, 16384]
    float* out = (float*)d_out;               // [128, 128]

    srl_gemm_kernel<<<NSPLIT, 512>>>(x, w);

    cudaLaunchConfig_t cfg = {};
    cfg.gridDim  = dim3(B_DIM);
    cfg.blockDim = dim3(256);
    cfg.dynamicSmemBytes = 0;
    cfg.stream = 0;
    cudaLaunchAttribute attr[1];
    attr[0].id = cudaLaunchAttributeProgrammaticStreamSerialization;
    attr[0].val.programmaticStreamSerializationAllowed = 1;
    cfg.attrs = attr;
    cfg.numAttrs = 1;
    cudaLaunchKernelEx(&cfg, srl_finalize_kernel, out);
}

// round 13
// speedup vs baseline: 1.2574x; 1.1201x over previous
#include <cuda_runtime.h>
#include <cuda_bf16.h>
#include <cuda_fp16.h>
#include <cstdint>

// ============================================================================
// out[b,o] = log( sum_k e^x[b,k] * e^w[o,k] ) - log( sum_k e^w[o,k] )
// GEMM: warp-specialized. 8 producer warps (LDG+exp+STS) / 8 consumer warps
// (ldmatrix+mma.sync) over 2-deep smem buffers with named barriers -> MUFU,
// LSU and tensor pipes run concurrently. Split-K 128; fp16 partials.
// Finalize: best-measured R4 shape (128 x 1024).
// ============================================================================

#define B_DIM  128
#define O_DIM  128
#define K_DIM  16384
#define NSPLIT 128
#define KCHUNK 128
#define NSUB   4
#define KSUB   32
#define LDSR   40     // smem row stride (bf16): 80B, conflict-free ldmatrix

// named barrier ids (0 reserved for __syncthreads)
#define BAR_FULL0  1
#define BAR_FULL1  2
#define BAR_EMPTY0 3
#define BAR_EMPTY1 4

__device__ __half2 g_part[NSPLIT * B_DIM * (O_DIM / 2)];  // [sp][b][o2] 4MB
__device__ float   g_rpart[NSPLIT * O_DIM];               // [sp][o]

__device__ __forceinline__ uint32_t smem_u32(const void* p) {
    return (uint32_t)__cvta_generic_to_shared(p);
}
__device__ __forceinline__ uint32_t bf2_bits(__nv_bfloat162 v) {
    union { __nv_bfloat162 h; uint32_t u; } cvt; cvt.h = v; return cvt.u;
}
__device__ __forceinline__ void bar_sync(int id) {
    asm volatile("bar.sync %0, 512;" :: "r"(id) : "memory");
}
__device__ __forceinline__ void bar_arrive(int id) {
    asm volatile("bar.arrive %0, 512;" :: "r"(id) : "memory");
}

__global__ __launch_bounds__(512, 1)
void srl_gemm_kernel(const float* __restrict__ x, const float* __restrict__ w) {
    __shared__ __align__(16) __nv_bfloat16 sA[2][B_DIM * LDSR];
    __shared__ __align__(16) __nv_bfloat16 sB[2][B_DIM * LDSR];

    const int tid  = threadIdx.x;
    const int lane = tid & 31;
    const int wid  = tid >> 5;
    const int bid  = blockIdx.x;
    const int kbase = bid * KCHUNK;

    if (wid < 8) {
        // ---------------- PRODUCERS (threads 0..255) ----------------
        // 2 threads per row; each owns 16 contiguous k (64B) per stage.
        const int row = tid >> 1;          // 0..127
        const int kh  = tid & 1;
        const float4* xp4 = (const float4*)(x + (size_t)row * K_DIM + kbase + kh * 16);
        const float4* wp4 = (const float4*)(w + (size_t)row * K_DIM + kbase + kh * 16);

        float4 rx[4], rw[4];
#pragma unroll
        for (int j = 0; j < 4; j++) { rx[j] = xp4[j]; rw[j] = wp4[j]; }

        float rsum = 0.f;

        for (int sub = 0; sub < NSUB; ++sub) {
            const int buf = sub & 1;
            const bool has_next = (sub + 1 < NSUB);

            if (sub >= 2) bar_sync(buf ? BAR_EMPTY1 : BAR_EMPTY0);

            uint2* adst = (uint2*)&sA[buf][row * LDSR + kh * 16];
            uint2* bdst = (uint2*)&sB[buf][row * LDSR + kh * 16];
#pragma unroll
            for (int j = 0; j < 4; j++) {
                float ax = __expf(rx[j].x), ay = __expf(rx[j].y);
                float az = __expf(rx[j].z), aw = __expf(rx[j].w);
                if (has_next) rx[j] = xp4[(sub + 1) * 8 + j];
                uint2 av;
                av.x = bf2_bits(__floats2bfloat162_rn(ax, ay));
                av.y = bf2_bits(__floats2bfloat162_rn(az, aw));
                adst[j] = av;
                float bx = __expf(rw[j].x), by = __expf(rw[j].y);
                float bz = __expf(rw[j].z), bw = __expf(rw[j].w);
                if (has_next) rw[j] = wp4[(sub + 1) * 8 + j];
                rsum += (bx + by) + (bz + bw);
                uint2 bv;
                bv.x = bf2_bits(__floats2bfloat162_rn(bx, by));
                bv.y = bf2_bits(__floats2bfloat162_rn(bz, bw));
                bdst[j] = bv;
            }

            bar_arrive(buf ? BAR_FULL1 : BAR_FULL0);
        }

        // rsum: 2 threads per w-row
        rsum += __shfl_xor_sync(0xffffffffu, rsum, 1);
        if (kh == 0) g_rpart[bid * O_DIM + row] = rsum;

    } else {
        // ---------------- CONSUMERS (threads 256..511) ----------------
        const int cw = wid - 8;            // 0..7
        const int m0 = (cw >> 2) * 64;     // 2 (m) x 4 (n) grid of 64x32 tiles
        const int n0 = (cw & 3) * 32;

        float acc[4][4][4];
#pragma unroll
        for (int mi = 0; mi < 4; mi++)
#pragma unroll
            for (int nj = 0; nj < 4; nj++)
#pragma unroll
                for (int q = 0; q < 4; q++) acc[mi][nj][q] = 0.f;

        for (int sub = 0; sub < NSUB; ++sub) {
            const int buf = sub & 1;
            bar_sync(buf ? BAR_FULL1 : BAR_FULL0);

#pragma unroll
            for (int ks = 0; ks < KSUB; ks += 16) {
                uint32_t af[4][4];
#pragma unroll
                for (int mi = 0; mi < 4; mi++) {
                    int ar = m0 + mi * 16 + (lane & 15);
                    int ac = ks + (lane >> 4) * 8;
                    uint32_t addr = smem_u32(&sA[buf][ar * LDSR + ac]);
                    asm volatile(
                        "ldmatrix.sync.aligned.m8n8.x4.shared.b16 {%0,%1,%2,%3}, [%4];"
                        : "=r"(af[mi][0]), "=r"(af[mi][1]), "=r"(af[mi][2]), "=r"(af[mi][3])
                        : "r"(addr));
                }
                uint32_t bfr[2][4];
#pragma unroll
                for (int nb = 0; nb < 2; nb++) {
                    int g = lane >> 3, r = lane & 7;
                    int br = n0 + nb * 16 + (g >> 1) * 8 + r;
                    int bc = ks + (g & 1) * 8;
                    uint32_t addr = smem_u32(&sB[buf][br * LDSR + bc]);
                    asm volatile(
                        "ldmatrix.sync.aligned.m8n8.x4.shared.b16 {%0,%1,%2,%3}, [%4];"
                        : "=r"(bfr[nb][0]), "=r"(bfr[nb][1]), "=r"(bfr[nb][2]), "=r"(bfr[nb][3])
                        : "r"(addr));
                }
#pragma unroll
                for (int mi = 0; mi < 4; mi++)
#pragma unroll
                    for (int nj = 0; nj < 4; nj++) {
                        uint32_t b0 = bfr[nj >> 1][(nj & 1) * 2 + 0];
                        uint32_t b1 = bfr[nj >> 1][(nj & 1) * 2 + 1];
                        asm volatile(
                            "mma.sync.aligned.m16n8k16.row.col.f32.bf16.bf16.f32 "
                            "{%0,%1,%2,%3}, {%4,%5,%6,%7}, {%8,%9}, {%0,%1,%2,%3};"
                            : "+f"(acc[mi][nj][0]), "+f"(acc[mi][nj][1]),
                              "+f"(acc[mi][nj][2]), "+f"(acc[mi][nj][3])
                            : "r"(af[mi][0]), "r"(af[mi][1]), "r"(af[mi][2]), "r"(af[mi][3]),
                              "r"(b0), "r"(b1));
                    }
            }

            bar_arrive(buf ? BAR_EMPTY1 : BAR_EMPTY0);
        }

        // fp16 partial tile [sp][b][o2]
        __half2* dst = g_part + (size_t)bid * (B_DIM * 64);
#pragma unroll
        for (int mi = 0; mi < 4; mi++)
#pragma unroll
            for (int nj = 0; nj < 4; nj++) {
                int gr = m0 + mi * 16 + (lane >> 2);
                int gc = n0 + nj * 8 + (lane & 3) * 2;
                dst[gr * 64 + (gc >> 1)] =
                    __floats2half2_rn(acc[mi][nj][0], acc[mi][nj][1]);
                dst[(gr + 8) * 64 + (gc >> 1)] =
                    __floats2half2_rn(acc[mi][nj][2], acc[mi][nj][3]);
            }
    }
}

// Finalize (R4 best-measured shape): block b; 32 sp-groups x 32 o4-slots.
__global__ __launch_bounds__(1024)
void srl_finalize_kernel(float* __restrict__ out) {
    const int b  = blockIdx.x;
    const int t  = threadIdx.x;
    const int o4 = t & 31;
    const int sg = t >> 5;

    float s0 = 0.f, s1 = 0.f, s2 = 0.f, s3 = 0.f;
    float r0 = 0.f, r1 = 0.f, r2 = 0.f, r3 = 0.f;
#pragma unroll
    for (int i = 0; i < 4; i++) {
        int sp = sg + 32 * i;
        uint2 pv = *(const uint2*)&g_part[(size_t)sp * (B_DIM * 64) + b * 64 + o4 * 2];
        union { uint32_t u; __half2 h; } c0, c1;
        c0.u = pv.x; c1.u = pv.y;
        float2 v0 = __half22float2(c0.h);
        float2 v1 = __half22float2(c1.h);
        s0 += v0.x; s1 += v0.y; s2 += v1.x; s3 += v1.y;
        float4 rv = *(const float4*)&g_rpart[sp * O_DIM + o4 * 4];
        r0 += rv.x; r1 += rv.y; r2 += rv.z; r3 += rv.w;
    }

    __shared__ float ss[32 * 128];
    __shared__ float sr[32 * 128];
    *(float4*)&ss[sg * 128 + o4 * 4] = make_float4(s0, s1, s2, s3);
    *(float4*)&sr[sg * 128 + o4 * 4] = make_float4(r0, r1, r2, r3);
    __syncthreads();

    if (t < 128) {
        float S = 0.f, R = 0.f;
#pragma unroll
        for (int i = 0; i < 32; i++) {
            S += ss[i * 128 + t];
            R += sr[i * 128 + t];
        }
        out[b * O_DIM + t] = __logf(S) - __logf(R);
    }
}

extern "C" void kernel_launch(void* const* d_in, const int* in_sizes, int n_in,
                              void* d_out, int out_size) {
    (void)in_sizes; (void)n_in; (void)out_size;
    const float* x = (const float*)d_in[0];   // [128, 16384]
    const float* w = (const float*)d_in[1];   // [128, 16384]
    float* out = (float*)d_out;               // [128, 128]

    srl_gemm_kernel<<<NSPLIT, 512>>>(x, w);
    srl_finalize_kernel<<<B_DIM, 1024>>>(out);
}